// round 14
// baseline (speedup 1.0000x reference)
#include <cuda_runtime.h>
#include <cstdint>

#define DM 2048
#define DH 256
#define NH 16
#define MAXN 131072

// ---------------- scratch (no allocations allowed) ----------------
__device__ float g_w1r[DM * DH];          // w1 RNA-rounded to tf32 (same layout)
__device__ float g_logits[NH * MAXN];     // head-major
__device__ float g_vals[NH * MAXN];       // head-major
__device__ float g_head_max[NH];
__device__ float g_score_max[NH];

// ---------------- helpers ----------------
__device__ __forceinline__ float to_tf32(float x) {
    uint32_t u;
    asm("cvt.rna.tf32.f32 %0, %1;" : "=r"(u) : "f"(x));
    return __uint_as_float(u);
}
__device__ __forceinline__ void cp_async16(uint32_t dst, const void* src) {
    asm volatile("cp.async.cg.shared.global [%0], [%1], 16;" :: "r"(dst), "l"(src));
}
__device__ __forceinline__ void atomicMaxFloat(float* addr, float val) {
    int* ai = (int*)addr;
    int old = *ai;
    while (__int_as_float(old) < val) {
        int assumed = old;
        old = atomicCAS(ai, assumed, __float_as_int(val));
        if (old == assumed) break;
    }
}
__device__ __forceinline__ uint32_t smem_u32(const void* p) {
    return (uint32_t)__cvta_generic_to_shared(p);
}

// ---------------- kernel 0: init maxima ----------------
__global__ void init_kernel() {
    if (threadIdx.x < NH) {
        g_head_max[threadIdx.x]  = __int_as_float(0xff800000);
        g_score_max[threadIdx.x] = __int_as_float(0xff800000);
    }
}

// ---------------- kernel 1: RNA-round w1 to tf32 ----------------
__global__ void w1cvt_kernel(const float* __restrict__ w1) {
    for (int i = blockIdx.x * blockDim.x + threadIdx.x; i < DM * DH;
         i += gridDim.x * blockDim.x)
        g_w1r[i] = to_tf32(w1[i]);
}

// ---------------- kernel 2: fused GEMM + relu + head projection ----------------
// Block tile 64 (M) x 256 (N), BK=32, 2-stage cp.async pipeline, 2 CTAs/SM.
// 8 warps in 1x8 grid, warp tile 64x32, mma m16n8k8 tf32, acc = 64 regs.
#define BM 64
#define BK 32
#define NT (DM / BK)                 // 64 k-tiles
#define BKP 36                       // A smem row stride (conflict-free frag loads)
#define BNP 264                      // B smem row stride (conflict-free frag loads)
#define A_FL (BM * BKP)              // 2304 floats
#define B_FL (BK * BNP)              // 8448 floats
#define STG_FL (A_FL + B_FL)         // 10752 floats per stage
#define Y_STRIDE 264
#define QV_STRIDE 257
#define QV_OFF (BM * Y_STRIDE)                  // 16896
#define HMS_OFF (QV_OFF + 32 * QV_STRIDE)       // 25120
#define GEMM_SMEM_FLOATS (HMS_OFF + 8 * NH + 32)  // 25280 (covers 2 stages: 21504)
#define GEMM_SMEM_BYTES (GEMM_SMEM_FLOATS * 4)    // 101120 B -> 2 CTAs/SM

__global__ __launch_bounds__(256, 2)
void gemm_kernel(const float* __restrict__ x, const float* __restrict__ bias,
                 const float* __restrict__ qm, const float* __restrict__ vm, int n)
{
    extern __shared__ float sm[];
    const uint32_t sbase = smem_u32(sm);
    const int tid  = threadIdx.x;
    const int bm0  = blockIdx.x * BM;
    const int warp = tid >> 5, lane = tid & 31;
    const int wn = warp;                         // 1x8 warp grid, 32 cols each
    const int g = lane >> 2, tg = lane & 3;      // mma thread mapping

    float acc[4][4][4];
    #pragma unroll
    for (int a = 0; a < 4; a++)
        #pragma unroll
        for (int b = 0; b < 4; b++)
            #pragma unroll
            for (int c = 0; c < 4; c++) acc[a][b][c] = 0.f;

    // stage fill: A (64x32, stride 36) via cp.async (x truncates to tf32 in HMMA),
    //             B (32x256, stride 264) via cp.async from RNA-rounded g_w1r.
    auto fill = [&](int kt, int s) {
        const uint32_t sa = sbase + (uint32_t)(s * STG_FL) * 4;
        const uint32_t sb = sa + A_FL * 4;
        #pragma unroll
        for (int j = 0; j < 2; j++) {                  // A: 512 float4
            const int i = tid + j * 256, row = i >> 3, c = i & 7;
            int grow = bm0 + row; if (grow >= n) grow = n - 1;
            cp_async16(sa + (uint32_t)(row * BKP + c * 4) * 4,
                       x + (size_t)grow * DM + kt * BK + c * 4);
        }
        #pragma unroll
        for (int j = 0; j < 8; j++) {                  // B: 2048 float4
            const int i = tid + j * 256, row = i >> 6, c = i & 63;
            cp_async16(sb + (uint32_t)(row * BNP + c * 4) * 4,
                       g_w1r + (size_t)(kt * BK + row) * DH + c * 4);
        }
        asm volatile("cp.async.commit_group;" ::: "memory");
    };

    // prologue: both stages in flight
    fill(0, 0); fill(1, 1);

    for (int kt = 0; kt < NT; kt++) {
        if (kt < NT - 1) asm volatile("cp.async.wait_group 1;" ::: "memory");
        else             asm volatile("cp.async.wait_group 0;" ::: "memory");
        __syncthreads();                // stage kt&1 fully written by all warps

        const float* Asb = sm + (kt & 1) * STG_FL;
        const float* Bsb = Asb + A_FL;
        #pragma unroll
        for (int kk = 0; kk < 4; kk++) {
            uint32_t af[4][4], bf[4][2];
            #pragma unroll
            for (int tm = 0; tm < 4; tm++) {
                const float* p = Asb + (tm * 16 + g) * BKP + kk * 8 + tg;
                af[tm][0] = __float_as_uint(p[0]);
                af[tm][1] = __float_as_uint(p[8 * BKP]);
                af[tm][2] = __float_as_uint(p[4]);
                af[tm][3] = __float_as_uint(p[8 * BKP + 4]);
            }
            #pragma unroll
            for (int tn = 0; tn < 4; tn++) {
                const float* p = Bsb + (kk * 8 + tg) * BNP + wn * 32 + tn * 8 + g;
                bf[tn][0] = __float_as_uint(p[0]);
                bf[tn][1] = __float_as_uint(p[4 * BNP]);
            }
            #pragma unroll
            for (int tm = 0; tm < 4; tm++)
                #pragma unroll
                for (int tn = 0; tn < 4; tn++) {
                    asm volatile(
                        "mma.sync.aligned.m16n8k8.row.col.f32.tf32.tf32.f32 "
                        "{%0,%1,%2,%3}, {%4,%5,%6,%7}, {%8,%9}, {%0,%1,%2,%3};"
                        : "+f"(acc[tm][tn][0]), "+f"(acc[tm][tn][1]),
                          "+f"(acc[tm][tn][2]), "+f"(acc[tm][tn][3])
                        : "r"(af[tm][0]), "r"(af[tm][1]), "r"(af[tm][2]), "r"(af[tm][3]),
                          "r"(bf[tn][0]), "r"(bf[tn][1]));
                }
        }
        if (kt + 2 < NT) {
            __syncthreads();            // all warps done reading stage kt&1
            fill(kt + 2, kt & 1);
        }
    }
    __syncthreads();   // all warps done with stages before epilogue overwrite

    // ---- epilogue: bias + relu -> y tile in smem ----
    #pragma unroll
    for (int tn = 0; tn < 4; tn++) {
        const int c = wn * 32 + tn * 8 + tg * 2;
        const float b0 = __ldg(bias + c);
        const float b1v = __ldg(bias + c + 1);
        #pragma unroll
        for (int tm = 0; tm < 4; tm++) {
            const int r = tm * 16 + g;
            float2 lo = make_float2(fmaxf(acc[tm][tn][0] + b0, 0.f),
                                    fmaxf(acc[tm][tn][1] + b1v, 0.f));
            float2 hi = make_float2(fmaxf(acc[tm][tn][2] + b0, 0.f),
                                    fmaxf(acc[tm][tn][3] + b1v, 0.f));
            *(float2*)(sm + r * Y_STRIDE + c) = lo;
            *(float2*)(sm + (r + 8) * Y_STRIDE + c) = hi;
        }
    }
    // queries/values into smem (padded stride -> conflict-free broadcast)
    float* qv = sm + QV_OFF;
    for (int i = tid; i < 32 * DH; i += 256) {
        const int r = i >> 8, c = i & 255;
        qv[r * QV_STRIDE + c] = (r < NH) ? __ldg(qm + r * DH + c)
                                         : __ldg(vm + (r - NH) * DH + c);
    }
    __syncthreads();

    // ---- projection: logits/vals per (token, head) + fused per-head max ----
    const int head = tid & 15;
    const int tl0 = tid >> 4;           // 16 token slots; 4 tokens per thread
    float aL[4], aV[4];
    #pragma unroll
    for (int i = 0; i < 4; i++) { aL[i] = 0.f; aV[i] = 0.f; }
    const float* qrow = qv + head * QV_STRIDE;
    const float* vrow = qv + (head + NH) * QV_STRIDE;
    #pragma unroll 4
    for (int k = 0; k < DH; k++) {
        const float qk = qrow[k];
        const float vk = vrow[k];
        #pragma unroll
        for (int i = 0; i < 4; i++) {
            const float yv = sm[(tl0 + 16 * i) * Y_STRIDE + k];
            aL[i] += yv * qk;
            aV[i] += yv * vk;
        }
    }
    float m = __int_as_float(0xff800000);
    #pragma unroll
    for (int i = 0; i < 4; i++) {
        const int t = bm0 + tl0 + 16 * i;
        if (t < n) {
            g_logits[(size_t)head * n + t] = aL[i];
            g_vals[(size_t)head * n + t]   = aV[i];
            m = fmaxf(m, aL[i]);
        }
    }
    // lanes h and h+16 share a head: combine, then reduce 8 warps via smem
    m = fmaxf(m, __shfl_xor_sync(0xffffffffu, m, 16));
    float* hms = sm + HMS_OFF;       // 8 warps x 16 heads
    if (lane < 16) hms[warp * NH + lane] = m;
    __syncthreads();
    if (tid < NH) {
        float hm = hms[tid];
        #pragma unroll
        for (int w = 1; w < 8; w++) hm = fmaxf(hm, hms[w * NH + tid]);
        atomicMaxFloat(&g_head_max[tid], hm);
    }
}

// ---------------- kernel 3: windowed softmax-mean + per-head max ----------------
#define CHW 2048   // windows per block (256 thr x 8 consecutive windows each)
__global__ void window_kernel(int n, const int* __restrict__ wptr) {
    const int tid = threadIdx.x;
    int w = *wptr;
    if (w > n)  w = n;
    if (w > 64) w = 64;   // smem halo capacity; problem uses 64
    const int NW = n - w + 1;
    const int h  = blockIdx.y;
    const int t0 = blockIdx.x * CHW;
    if (t0 >= NW) return;

    __shared__ float es[CHW + 64], evs[CHW + 64];
    __shared__ float red[256];
    const float m = g_head_max[h];
    const int L = min(CHW + w - 1, n - t0);
    const float* lg = g_logits + (size_t)h * n + t0;
    const float* vl = g_vals   + (size_t)h * n + t0;
    for (int i = tid; i < L; i += 256) {
        const float e = expf(lg[i] - m);
        es[i]  = e;
        evs[i] = e * vl[i];
    }
    __syncthreads();

    float best = __int_as_float(0xff800000);
    const int rel = tid * 8;
    const int wb = t0 + rel;
    if (wb < NW) {
        float z = 0.f, zn = 0.f;
        for (int k = 0; k < w; k++) { z += es[rel + k]; zn += evs[rel + k]; }
        best = zn / z;
        #pragma unroll
        for (int j = 1; j < 8; j++) {
            if (wb + j >= NW) break;
            z  += es[rel + j - 1 + w]  - es[rel + j - 1];
            zn += evs[rel + j - 1 + w] - evs[rel + j - 1];
            best = fmaxf(best, zn / z);
        }
    }
    red[tid] = best;
    __syncthreads();
    for (int s = 128; s > 0; s >>= 1) {
        if (tid < s) red[tid] = fmaxf(red[tid], red[tid + s]);
        __syncthreads();
    }
    if (tid == 0) atomicMaxFloat(&g_score_max[h], red[0]);
}

// ---------------- kernel 4: final sum over heads ----------------
__global__ void final_kernel(float* out) {
    if (threadIdx.x == 0) {
        float s = 0.f;
        #pragma unroll
        for (int h = 0; h < NH; h++) s += g_score_max[h];
        out[0] = s;
    }
}

// ---------------- launch ----------------
extern "C" void kernel_launch(void* const* d_in, const int* in_sizes, int n_in,
                              void* d_out, int out_size) {
    const float* x  = (const float*)d_in[0];
    const float* w1 = (const float*)d_in[1];
    const float* b1 = (const float*)d_in[2];
    const float* qm = (const float*)d_in[3];
    const float* vm = (const float*)d_in[4];
    const int*   wp = (const int*)d_in[5];
    const int n = in_sizes[0] / DM;

    cudaFuncSetAttribute(gemm_kernel, cudaFuncAttributeMaxDynamicSharedMemorySize,
                         GEMM_SMEM_BYTES);

    init_kernel<<<1, 32>>>();
    w1cvt_kernel<<<256, 256>>>(w1);
    gemm_kernel<<<(n + BM - 1) / BM, 256, GEMM_SMEM_BYTES>>>(x, b1, qm, vm, n);
    window_kernel<<<dim3((n + CHW - 1) / CHW, NH), 256>>>(n, wp);
    final_kernel<<<1, 32>>>((float*)d_out);
}

// round 15
// speedup vs baseline: 1.0507x; 1.0507x over previous
#include <cuda_runtime.h>
#include <cstdint>

#define DM 2048
#define DH 256
#define NH 16
#define MAXN 131072

// ---------------- scratch (no allocations allowed) ----------------
__device__ float g_w1t[DH * DM];          // w1 transposed [256][2048], RNA tf32
__device__ float g_logits[NH * MAXN];     // head-major
__device__ float g_vals[NH * MAXN];       // head-major
__device__ float g_head_max[NH];
__device__ float g_score_max[NH];

// ---------------- helpers ----------------
__device__ __forceinline__ float to_tf32(float x) {
    uint32_t u;
    asm("cvt.rna.tf32.f32 %0, %1;" : "=r"(u) : "f"(x));
    return __uint_as_float(u);
}
__device__ __forceinline__ void cp_async16(uint32_t dst, const void* src) {
    asm volatile("cp.async.cg.shared.global [%0], [%1], 16;" :: "r"(dst), "l"(src));
}
__device__ __forceinline__ void atomicMaxFloat(float* addr, float val) {
    int* ai = (int*)addr;
    int old = *ai;
    while (__int_as_float(old) < val) {
        int assumed = old;
        old = atomicCAS(ai, assumed, __float_as_int(val));
        if (old == assumed) break;
    }
}
__device__ __forceinline__ uint32_t smem_u32(const void* p) {
    return (uint32_t)__cvta_generic_to_shared(p);
}
__device__ __forceinline__ void ldsm4(uint32_t* d, uint32_t a) {
    asm volatile("ldmatrix.sync.aligned.m8n8.x4.shared.b16 {%0,%1,%2,%3}, [%4];"
                 : "=r"(d[0]), "=r"(d[1]), "=r"(d[2]), "=r"(d[3]) : "r"(a));
}
__device__ __forceinline__ void ldsm2(uint32_t* d, uint32_t a) {
    asm volatile("ldmatrix.sync.aligned.m8n8.x2.shared.b16 {%0,%1}, [%2];"
                 : "=r"(d[0]), "=r"(d[1]) : "r"(a));
}

// ---------------- kernel 0: init maxima ----------------
__global__ void init_kernel() {
    if (threadIdx.x < NH) {
        g_head_max[threadIdx.x]  = __int_as_float(0xff800000);
        g_score_max[threadIdx.x] = __int_as_float(0xff800000);
    }
}

// ---------------- kernel 1: transpose + RNA-round w1 -> g_w1t[n][k] ----------------
__global__ void w1cvt_kernel(const float* __restrict__ w1) {
    __shared__ float t[32][33];
    const int kt = blockIdx.x, nt = blockIdx.y;
    const int tx = threadIdx.x & 31, ty = threadIdx.x >> 5;   // 256 thr: ty 0..7
    #pragma unroll
    for (int j = 0; j < 32; j += 8)
        t[ty + j][tx] = w1[(size_t)(kt * 32 + ty + j) * DH + nt * 32 + tx];
    __syncthreads();
    #pragma unroll
    for (int j = 0; j < 32; j += 8)
        g_w1t[(size_t)(nt * 32 + ty + j) * DM + kt * 32 + tx] = to_tf32(t[tx][ty + j]);
}

// ---------------- kernel 2: fused GEMM + relu + head projection ----------------
// Block tile 128 (M) x 256 (N), BK=32, 4-stage cp.async pipeline, ldmatrix frags.
// 8 warps in 2x4 grid, warp tile 64x64, mma m16n8k8 tf32.
#define BM 128
#define BK 32
#define NT (DM / BK)                 // 64 k-tiles
#define NSTG 4
#define RSP 36                       // smem row stride (floats) for A and B rows
#define A_FL (BM * RSP)              // 4608 floats (128 m-rows x 32 k)
#define B_FL (DH * RSP)              // 9216 floats (256 n-rows x 32 k)
#define STG_FL (A_FL + B_FL)         // 13824 floats per stage
#define Y_STRIDE 264
#define QV_STRIDE 257
#define QV_OFF (BM * Y_STRIDE)                  // 33792
#define HMS_OFF (QV_OFF + 32 * QV_STRIDE)       // 42016
#define GEMM_SMEM_FLOATS (NSTG * STG_FL)        // 55296 (covers epilogue 42144)
#define GEMM_SMEM_BYTES (GEMM_SMEM_FLOATS * 4)  // 221184 B

__global__ __launch_bounds__(256, 1)
void gemm_kernel(const float* __restrict__ x, const float* __restrict__ bias,
                 const float* __restrict__ qm, const float* __restrict__ vm, int n)
{
    extern __shared__ float sm[];
    const uint32_t sbase = smem_u32(sm);
    const int tid  = threadIdx.x;
    const int bm0  = blockIdx.x * BM;
    const int warp = tid >> 5, lane = tid & 31;
    const int wm = warp >> 2, wn = warp & 3;     // 2x4 warp grid
    const int g = lane >> 2, tg = lane & 3;      // mma thread mapping
    (void)g; (void)tg;

    float acc[4][8][4];
    #pragma unroll
    for (int a = 0; a < 4; a++)
        #pragma unroll
        for (int b = 0; b < 8; b++)
            #pragma unroll
            for (int c = 0; c < 4; c++) acc[a][b][c] = 0.f;

    // ldmatrix per-lane address offsets (bytes, within a stage)
    // A: x4 -> lane groups q=lane>>3: (q&1)->m+8, (q>>1)->k+4
    const int lq = lane >> 3, lr = lane & 7;
    uint32_t a_off[4], b_off[8];
    #pragma unroll
    for (int tm = 0; tm < 4; tm++)
        a_off[tm] = (uint32_t)(((wm * 64 + tm * 16 + (lq & 1) * 8 + lr) * RSP
                                + (lq >> 1) * 4) * 4);
    // B: x2 -> lanes 0-15 addresses; q2=(lane>>3)&1 -> k+4 (lanes 16-31 mirror)
    const int q2 = lq & 1;
    #pragma unroll
    for (int tn = 0; tn < 8; tn++)
        b_off[tn] = (uint32_t)(A_FL * 4
                    + ((wn * 64 + tn * 8 + lr) * RSP + q2 * 4) * 4);

    // stage fill: A (128 m-rows x 32k) from x (truncates to tf32 in HMMA),
    //             B (256 n-rows x 32k) from RNA-rounded transposed g_w1t.
    auto fill = [&](int kt, int s) {
        const uint32_t sa = sbase + (uint32_t)(s * STG_FL) * 4;
        const uint32_t sb = sa + A_FL * 4;
        #pragma unroll
        for (int j = 0; j < 4; j++) {                  // A: 1024 float4
            const int i = tid + j * 256, row = i >> 3, c = i & 7;
            int grow = bm0 + row; if (grow >= n) grow = n - 1;
            cp_async16(sa + (uint32_t)(row * RSP + c * 4) * 4,
                       x + (size_t)grow * DM + kt * BK + c * 4);
        }
        #pragma unroll
        for (int j = 0; j < 8; j++) {                  // B: 2048 float4
            const int i = tid + j * 256, row = i >> 3, c = i & 7;
            cp_async16(sb + (uint32_t)(row * RSP + c * 4) * 4,
                       g_w1t + (size_t)row * DM + kt * BK + c * 4);
        }
        asm volatile("cp.async.commit_group;" ::: "memory");
    };

    // prologue: 3 stages in flight
    fill(0, 0); fill(1, 1); fill(2, 2);

    for (int kt = 0; kt < NT; kt++) {
        const int rem = NT - 1 - kt;
        if (rem >= 2)      asm volatile("cp.async.wait_group 2;" ::: "memory");
        else if (rem == 1) asm volatile("cp.async.wait_group 1;" ::: "memory");
        else               asm volatile("cp.async.wait_group 0;" ::: "memory");
        __syncthreads();

        const uint32_t stg = sbase + (uint32_t)((kt & 3) * STG_FL) * 4;
        #pragma unroll
        for (int kk = 0; kk < 4; kk++) {
            uint32_t af[4][4], bf[8][2];
            #pragma unroll
            for (int tm = 0; tm < 4; tm++)
                ldsm4(af[tm], stg + a_off[tm] + kk * 32);
            #pragma unroll
            for (int tn = 0; tn < 8; tn++)
                ldsm2(bf[tn], stg + b_off[tn] + kk * 32);
            #pragma unroll
            for (int tm = 0; tm < 4; tm++)
                #pragma unroll
                for (int tn = 0; tn < 8; tn++) {
                    asm volatile(
                        "mma.sync.aligned.m16n8k8.row.col.f32.tf32.tf32.f32 "
                        "{%0,%1,%2,%3}, {%4,%5,%6,%7}, {%8,%9}, {%0,%1,%2,%3};"
                        : "+f"(acc[tm][tn][0]), "+f"(acc[tm][tn][1]),
                          "+f"(acc[tm][tn][2]), "+f"(acc[tm][tn][3])
                        : "r"(af[tm][0]), "r"(af[tm][1]), "r"(af[tm][2]), "r"(af[tm][3]),
                          "r"(bf[tn][0]), "r"(bf[tn][1]));
                }
        }
        const int nk = kt + 3;
        if (nk < NT) fill(nk, nk & 3);
    }
    __syncthreads();   // all warps done reading stages before epilogue overwrite

    // ---- epilogue: bias + relu -> y tile in smem ----
    const int tg4 = lane & 3, g8 = lane >> 2;
    #pragma unroll
    for (int tn = 0; tn < 8; tn++) {
        const int c = wn * 64 + tn * 8 + tg4 * 2;
        const float b0 = __ldg(bias + c);
        const float b1v = __ldg(bias + c + 1);
        #pragma unroll
        for (int tm = 0; tm < 4; tm++) {
            const int r = wm * 64 + tm * 16 + g8;
            float2 lo = make_float2(fmaxf(acc[tm][tn][0] + b0, 0.f),
                                    fmaxf(acc[tm][tn][1] + b1v, 0.f));
            float2 hi = make_float2(fmaxf(acc[tm][tn][2] + b0, 0.f),
                                    fmaxf(acc[tm][tn][3] + b1v, 0.f));
            *(float2*)(sm + r * Y_STRIDE + c) = lo;
            *(float2*)(sm + (r + 8) * Y_STRIDE + c) = hi;
        }
    }
    // queries/values into smem (padded stride -> conflict-free broadcast)
    float* qv = sm + QV_OFF;
    for (int i = tid; i < 32 * DH; i += 256) {
        const int r = i >> 8, c = i & 255;
        qv[r * QV_STRIDE + c] = (r < NH) ? __ldg(qm + r * DH + c)
                                         : __ldg(vm + (r - NH) * DH + c);
    }
    __syncthreads();

    // ---- projection: logits/vals per (token, head) + fused per-head max ----
    const int head = tid & 15;
    const int tl0 = tid >> 4;
    float aL[8], aV[8];
    #pragma unroll
    for (int i = 0; i < 8; i++) { aL[i] = 0.f; aV[i] = 0.f; }
    const float* qrow = qv + head * QV_STRIDE;
    const float* vrow = qv + (head + NH) * QV_STRIDE;
    #pragma unroll 4
    for (int k = 0; k < DH; k++) {
        const float qk = qrow[k];
        const float vk = vrow[k];
        #pragma unroll
        for (int i = 0; i < 8; i++) {
            const float yv = sm[(tl0 + 16 * i) * Y_STRIDE + k];
            aL[i] += yv * qk;
            aV[i] += yv * vk;
        }
    }
    float m = __int_as_float(0xff800000);
    #pragma unroll
    for (int i = 0; i < 8; i++) {
        const int t = bm0 + tl0 + 16 * i;
        if (t < n) {
            g_logits[(size_t)head * n + t] = aL[i];
            g_vals[(size_t)head * n + t]   = aV[i];
            m = fmaxf(m, aL[i]);
        }
    }
    // lanes h and h+16 share a head: combine, then reduce 8 warps via smem
    m = fmaxf(m, __shfl_xor_sync(0xffffffffu, m, 16));
    float* hms = sm + HMS_OFF;       // 8 warps x 16 heads
    if (lane < 16) hms[warp * NH + lane] = m;
    __syncthreads();
    if (tid < NH) {
        float hm = hms[tid];
        #pragma unroll
        for (int w = 1; w < 8; w++) hm = fmaxf(hm, hms[w * NH + tid]);
        atomicMaxFloat(&g_head_max[tid], hm);
    }
}

// ---------------- kernel 3: windowed softmax-mean + per-head max ----------------
#define CHW 2048   // windows per block (256 thr x 8 consecutive windows each)
__global__ void window_kernel(int n, const int* __restrict__ wptr) {
    const int tid = threadIdx.x;
    int w = *wptr;
    if (w > n)  w = n;
    if (w > 64) w = 64;   // smem halo capacity; problem uses 64
    const int NW = n - w + 1;
    const int h  = blockIdx.y;
    const int t0 = blockIdx.x * CHW;
    if (t0 >= NW) return;

    __shared__ float es[CHW + 64], evs[CHW + 64];
    __shared__ float red[256];
    const float m = g_head_max[h];
    const int L = min(CHW + w - 1, n - t0);
    const float* lg = g_logits + (size_t)h * n + t0;
    const float* vl = g_vals   + (size_t)h * n + t0;
    for (int i = tid; i < L; i += 256) {
        const float e = expf(lg[i] - m);
        es[i]  = e;
        evs[i] = e * vl[i];
    }
    __syncthreads();

    float best = __int_as_float(0xff800000);
    const int rel = tid * 8;
    const int wb = t0 + rel;
    if (wb < NW) {
        float z = 0.f, zn = 0.f;
        for (int k = 0; k < w; k++) { z += es[rel + k]; zn += evs[rel + k]; }
        best = zn / z;
        #pragma unroll
        for (int j = 1; j < 8; j++) {
            if (wb + j >= NW) break;
            z  += es[rel + j - 1 + w]  - es[rel + j - 1];
            zn += evs[rel + j - 1 + w] - evs[rel + j - 1];
            best = fmaxf(best, zn / z);
        }
    }
    red[tid] = best;
    __syncthreads();
    for (int s = 128; s > 0; s >>= 1) {
        if (tid < s) red[tid] = fmaxf(red[tid], red[tid + s]);
        __syncthreads();
    }
    if (tid == 0) atomicMaxFloat(&g_score_max[h], red[0]);
}

// ---------------- kernel 4: final sum over heads ----------------
__global__ void final_kernel(float* out) {
    if (threadIdx.x == 0) {
        float s = 0.f;
        #pragma unroll
        for (int h = 0; h < NH; h++) s += g_score_max[h];
        out[0] = s;
    }
}

// ---------------- launch ----------------
extern "C" void kernel_launch(void* const* d_in, const int* in_sizes, int n_in,
                              void* d_out, int out_size) {
    const float* x  = (const float*)d_in[0];
    const float* w1 = (const float*)d_in[1];
    const float* b1 = (const float*)d_in[2];
    const float* qm = (const float*)d_in[3];
    const float* vm = (const float*)d_in[4];
    const int*   wp = (const int*)d_in[5];
    const int n = in_sizes[0] / DM;

    cudaFuncSetAttribute(gemm_kernel, cudaFuncAttributeMaxDynamicSharedMemorySize,
                         GEMM_SMEM_BYTES);

    init_kernel<<<1, 32>>>();
    w1cvt_kernel<<<dim3(DM / 32, DH / 32), 256>>>(w1);
    gemm_kernel<<<(n + BM - 1) / BM, 256, GEMM_SMEM_BYTES>>>(x, b1, qm, vm, n);
    window_kernel<<<dim3((n + CHW - 1) / CHW, NH), 256>>>(n, wp);
    final_kernel<<<1, 32>>>((float*)d_out);
}

// round 16
// speedup vs baseline: 1.5550x; 1.4800x over previous
#include <cuda_runtime.h>
#include <cuda_fp16.h>
#include <cstdint>

#define DM 2048
#define DH 256
#define NH 16
#define MAXN 131072

// ---------------- scratch (no allocations allowed) ----------------
__device__ __half g_w1h[DH * DM];         // w1 transposed [256][2048], fp16 RN
__device__ float g_logits[NH * MAXN];     // head-major
__device__ float g_vals[NH * MAXN];       // head-major
__device__ float g_head_max[NH];
__device__ float g_score_max[NH];

// ---------------- helpers ----------------
__device__ __forceinline__ void cp_async16(uint32_t dst, const void* src) {
    asm volatile("cp.async.cg.shared.global [%0], [%1], 16;" :: "r"(dst), "l"(src));
}
__device__ __forceinline__ void atomicMaxFloat(float* addr, float val) {
    int* ai = (int*)addr;
    int old = *ai;
    while (__int_as_float(old) < val) {
        int assumed = old;
        old = atomicCAS(ai, assumed, __float_as_int(val));
        if (old == assumed) break;
    }
}
__device__ __forceinline__ uint32_t smem_u32(const void* p) {
    return (uint32_t)__cvta_generic_to_shared(p);
}
__device__ __forceinline__ void ldsm4(uint32_t* d, uint32_t a) {
    asm volatile("ldmatrix.sync.aligned.m8n8.x4.shared.b16 {%0,%1,%2,%3}, [%4];"
                 : "=r"(d[0]), "=r"(d[1]), "=r"(d[2]), "=r"(d[3]) : "r"(a));
}
__device__ __forceinline__ void ldsm2(uint32_t* d, uint32_t a) {
    asm volatile("ldmatrix.sync.aligned.m8n8.x2.shared.b16 {%0,%1}, [%2];"
                 : "=r"(d[0]), "=r"(d[1]) : "r"(a));
}
__device__ __forceinline__ uint32_t pack_h2(float a, float b) {
    __half2 h = __floats2half2_rn(a, b);
    return *(uint32_t*)&h;
}

// ---------------- kernel 0: init maxima ----------------
__global__ void init_kernel() {
    if (threadIdx.x < NH) {
        g_head_max[threadIdx.x]  = __int_as_float(0xff800000);
        g_score_max[threadIdx.x] = __int_as_float(0xff800000);
    }
}

// ---------------- kernel 1: transpose + RN-convert w1 -> g_w1h[n][k] ----------------
__global__ void w1cvt_kernel(const float* __restrict__ w1) {
    __shared__ float t[32][33];
    const int kt = blockIdx.x, nt = blockIdx.y;
    const int tx = threadIdx.x & 31, ty = threadIdx.x >> 5;   // 256 thr: ty 0..7
    #pragma unroll
    for (int j = 0; j < 32; j += 8)
        t[ty + j][tx] = w1[(size_t)(kt * 32 + ty + j) * DH + nt * 32 + tx];
    __syncthreads();
    #pragma unroll
    for (int j = 0; j < 32; j += 8)
        g_w1h[(size_t)(nt * 32 + ty + j) * DM + kt * 32 + tx] =
            __float2half_rn(t[tx][ty + j]);
}

// ---------------- kernel 2: fused GEMM(fp16 HMMA) + relu + head projection ----
// Block tile 128 (M) x 256 (N), BK=32, 4 stages.
// B (w1h) via cp.async; A (x) via LDG->cvt fp16->STS register pipeline (dist 2-3).
// 8 warps in 2x4 grid, warp tile 64x64, mma m16n8k16 f16 (fp32 accum).
#define BM 128
#define BK 32
#define NT (DM / BK)                 // 64 k-tiles
#define RSB 80                       // smem row stride BYTES (40 halves): 16B-aligned,
                                     // conflict-free (5r mod 8 distinct 16B lanes)
#define A_BY (BM * RSB)              // 10240 B per stage
#define B_BY (DH * RSB)              // 20480 B per stage
#define STG_BY (A_BY + B_BY)         // 30720 B per stage
#define Y_STRIDE 264
#define QV_STRIDE 257
#define QV_OFF (BM * Y_STRIDE)                  // 33792 floats
#define HMS_OFF (QV_OFF + 32 * QV_STRIDE)       // 42016
#define GEMM_SMEM_FLOATS (HMS_OFF + 8 * NH + 32)   // 42176 floats = 168704 B
#define GEMM_SMEM_BYTES (GEMM_SMEM_FLOATS * 4)     // covers 4 stages (122880 B)

__global__ __launch_bounds__(256, 1)
void gemm_kernel(const float* __restrict__ x, const float* __restrict__ bias,
                 const float* __restrict__ qm, const float* __restrict__ vm, int n)
{
    extern __shared__ float sm[];
    const uint32_t sbase = smem_u32(sm);
    const int tid  = threadIdx.x;
    const int bm0  = blockIdx.x * BM;
    const int warp = tid >> 5, lane = tid & 31;
    const int wm = warp >> 2, wn = warp & 3;     // 2x4 warp grid

    float acc[4][8][4];
    #pragma unroll
    for (int a = 0; a < 4; a++)
        #pragma unroll
        for (int b = 0; b < 8; b++)
            #pragma unroll
            for (int c = 0; c < 4; c++) acc[a][b][c] = 0.f;

    // per-thread A-fill mapping: 1024 float4 = 128 rows x 8 cols
    const int arow = tid >> 1;                    // with j-loop: i=tid+j*256
    (void)arow;

    // ldmatrix address offsets (bytes within a stage)
    uint32_t aoff[4], boff[8];
    #pragma unroll
    for (int tm = 0; tm < 4; tm++)
        aoff[tm] = (uint32_t)((wm * 64 + tm * 16 + (lane & 15)) * RSB
                              + (lane >> 4) * 16);
    #pragma unroll
    for (int tn = 0; tn < 8; tn++)
        boff[tn] = (uint32_t)(A_BY + (wn * 64 + tn * 8 + (lane & 7)) * RSB
                              + ((lane >> 3) & 1) * 16);

    float4 areg[4];
    auto ldgA = [&](int kt) {
        #pragma unroll
        for (int j = 0; j < 4; j++) {
            const int i = tid + j * 256, row = i >> 3, c = i & 7;
            int grow = bm0 + row; if (grow >= n) grow = n - 1;
            areg[j] = *(const float4*)(x + (size_t)grow * DM + kt * BK + c * 4);
        }
    };
    auto stsA = [&](int s) {
        const uint32_t sa = sbase + (uint32_t)(s * STG_BY);
        #pragma unroll
        for (int j = 0; j < 4; j++) {
            const int i = tid + j * 256, row = i >> 3, c = i & 7;
            uint2 h;
            h.x = pack_h2(areg[j].x, areg[j].y);
            h.y = pack_h2(areg[j].z, areg[j].w);
            *(uint2*)((char*)sm + (sa - sbase) + row * RSB + c * 8) = h;
        }
    };
    auto fillB = [&](int kt, int s) {
        const uint32_t sb = sbase + (uint32_t)(s * STG_BY) + A_BY;
        #pragma unroll
        for (int j = 0; j < 4; j++) {                  // 256 rows x 4 x 16B
            const int i = tid + j * 256, row = i >> 2, c = i & 3;
            cp_async16(sb + (uint32_t)(row * RSB + c * 16),
                       g_w1h + (size_t)row * DM + kt * BK + c * 8);
        }
        asm volatile("cp.async.commit_group;" ::: "memory");
    };

    // prologue: A stages 0,1 stored; A(2) held in regs; B stages 0-2 in flight
    ldgA(0); stsA(0);
    ldgA(1); stsA(1);
    ldgA(2);
    fillB(0, 0); fillB(1, 1); fillB(2, 2);

    for (int kt = 0; kt < NT; kt++) {
        const int rem = NT - 1 - kt;
        if (rem >= 2)      asm volatile("cp.async.wait_group 2;" ::: "memory");
        else if (rem == 1) asm volatile("cp.async.wait_group 1;" ::: "memory");
        else               asm volatile("cp.async.wait_group 0;" ::: "memory");
        __syncthreads();

        // A register pipeline: store A(kt+2) (held in regs) into its stage,
        // then start loading A(kt+3). Stage (kt+2)&3 has no readers now
        // (all warps are inside tile kt); 2 barriers before its consumption.
        if (kt + 2 < NT) stsA((kt + 2) & 3);
        if (kt + 3 < NT) ldgA(kt + 3);

        const uint32_t stg = sbase + (uint32_t)((kt & 3) * STG_BY);
        #pragma unroll
        for (int kc = 0; kc < 2; kc++) {          // two k16 chunks
            uint32_t af[4][4], bf[8][2];
            #pragma unroll
            for (int tm = 0; tm < 4; tm++)
                ldsm4(af[tm], stg + aoff[tm] + kc * 32);
            #pragma unroll
            for (int tn = 0; tn < 8; tn++)
                ldsm2(bf[tn], stg + boff[tn] + kc * 32);
            #pragma unroll
            for (int tm = 0; tm < 4; tm++)
                #pragma unroll
                for (int tn = 0; tn < 8; tn++) {
                    asm volatile(
                        "mma.sync.aligned.m16n8k16.row.col.f32.f16.f16.f32 "
                        "{%0,%1,%2,%3}, {%4,%5,%6,%7}, {%8,%9}, {%0,%1,%2,%3};"
                        : "+f"(acc[tm][tn][0]), "+f"(acc[tm][tn][1]),
                          "+f"(acc[tm][tn][2]), "+f"(acc[tm][tn][3])
                        : "r"(af[tm][0]), "r"(af[tm][1]),
                          "r"(af[tm][2]), "r"(af[tm][3]),
                          "r"(bf[tn][0]), "r"(bf[tn][1]));
                }
        }
        if (kt + 3 < NT) fillB(kt + 3, (kt + 3) & 3);
    }
    __syncthreads();   // all warps done with stages before epilogue overwrite

    // ---- epilogue: bias + relu -> y tile in smem ----
    const int tg4 = lane & 3, g8 = lane >> 2;
    #pragma unroll
    for (int tn = 0; tn < 8; tn++) {
        const int c = wn * 64 + tn * 8 + tg4 * 2;
        const float b0 = __ldg(bias + c);
        const float b1v = __ldg(bias + c + 1);
        #pragma unroll
        for (int tm = 0; tm < 4; tm++) {
            const int r = wm * 64 + tm * 16 + g8;
            float2 lo = make_float2(fmaxf(acc[tm][tn][0] + b0, 0.f),
                                    fmaxf(acc[tm][tn][1] + b1v, 0.f));
            float2 hi = make_float2(fmaxf(acc[tm][tn][2] + b0, 0.f),
                                    fmaxf(acc[tm][tn][3] + b1v, 0.f));
            *(float2*)(sm + r * Y_STRIDE + c) = lo;
            *(float2*)(sm + (r + 8) * Y_STRIDE + c) = hi;
        }
    }
    // queries/values into smem (padded stride -> conflict-free broadcast)
    float* qv = sm + QV_OFF;
    for (int i = tid; i < 32 * DH; i += 256) {
        const int r = i >> 8, c = i & 255;
        qv[r * QV_STRIDE + c] = (r < NH) ? __ldg(qm + r * DH + c)
                                         : __ldg(vm + (r - NH) * DH + c);
    }
    __syncthreads();

    // ---- projection: logits/vals per (token, head) + fused per-head max ----
    const int head = tid & 15;
    const int tl0 = tid >> 4;
    float aL[8], aV[8];
    #pragma unroll
    for (int i = 0; i < 8; i++) { aL[i] = 0.f; aV[i] = 0.f; }
    const float* qrow = qv + head * QV_STRIDE;
    const float* vrow = qv + (head + NH) * QV_STRIDE;
    #pragma unroll 4
    for (int k = 0; k < DH; k++) {
        const float qk = qrow[k];
        const float vk = vrow[k];
        #pragma unroll
        for (int i = 0; i < 8; i++) {
            const float yv = sm[(tl0 + 16 * i) * Y_STRIDE + k];
            aL[i] += yv * qk;
            aV[i] += yv * vk;
        }
    }
    float m = __int_as_float(0xff800000);
    #pragma unroll
    for (int i = 0; i < 8; i++) {
        const int t = bm0 + tl0 + 16 * i;
        if (t < n) {
            g_logits[(size_t)head * n + t] = aL[i];
            g_vals[(size_t)head * n + t]   = aV[i];
            m = fmaxf(m, aL[i]);
        }
    }
    // lanes h and h+16 share a head: combine, then reduce 8 warps via smem
    m = fmaxf(m, __shfl_xor_sync(0xffffffffu, m, 16));
    float* hms = sm + HMS_OFF;       // 8 warps x 16 heads
    if (lane < 16) hms[warp * NH + lane] = m;
    __syncthreads();
    if (tid < NH) {
        float hm = hms[tid];
        #pragma unroll
        for (int w = 1; w < 8; w++) hm = fmaxf(hm, hms[w * NH + tid]);
        atomicMaxFloat(&g_head_max[tid], hm);
    }
}

// ---------------- kernel 3: windowed softmax-mean + per-head max ----------------
#define CHW 2048   // windows per block (256 thr x 8 consecutive windows each)
__global__ void window_kernel(int n, const int* __restrict__ wptr) {
    const int tid = threadIdx.x;
    int w = *wptr;
    if (w > n)  w = n;
    if (w > 64) w = 64;   // smem halo capacity; problem uses 64
    const int NW = n - w + 1;
    const int h  = blockIdx.y;
    const int t0 = blockIdx.x * CHW;
    if (t0 >= NW) return;

    __shared__ float es[CHW + 64], evs[CHW + 64];
    __shared__ float red[256];
    const float m = g_head_max[h];
    const int L = min(CHW + w - 1, n - t0);
    const float* lg = g_logits + (size_t)h * n + t0;
    const float* vl = g_vals   + (size_t)h * n + t0;
    for (int i = tid; i < L; i += 256) {
        const float e = expf(lg[i] - m);
        es[i]  = e;
        evs[i] = e * vl[i];
    }
    __syncthreads();

    float best = __int_as_float(0xff800000);
    const int rel = tid * 8;
    const int wb = t0 + rel;
    if (wb < NW) {
        float z = 0.f, zn = 0.f;
        for (int k = 0; k < w; k++) { z += es[rel + k]; zn += evs[rel + k]; }
        best = zn / z;
        #pragma unroll
        for (int j = 1; j < 8; j++) {
            if (wb + j >= NW) break;
            z  += es[rel + j - 1 + w]  - es[rel + j - 1];
            zn += evs[rel + j - 1 + w] - evs[rel + j - 1];
            best = fmaxf(best, zn / z);
        }
    }
    red[tid] = best;
    __syncthreads();
    for (int s = 128; s > 0; s >>= 1) {
        if (tid < s) red[tid] = fmaxf(red[tid], red[tid + s]);
        __syncthreads();
    }
    if (tid == 0) atomicMaxFloat(&g_score_max[h], red[0]);
}

// ---------------- kernel 4: final sum over heads ----------------
__global__ void final_kernel(float* out) {
    if (threadIdx.x == 0) {
        float s = 0.f;
        #pragma unroll
        for (int h = 0; h < NH; h++) s += g_score_max[h];
        out[0] = s;
    }
}

// ---------------- launch ----------------
extern "C" void kernel_launch(void* const* d_in, const int* in_sizes, int n_in,
                              void* d_out, int out_size) {
    const float* x  = (const float*)d_in[0];
    const float* w1 = (const float*)d_in[1];
    const float* b1 = (const float*)d_in[2];
    const float* qm = (const float*)d_in[3];
    const float* vm = (const float*)d_in[4];
    const int*   wp = (const int*)d_in[5];
    const int n = in_sizes[0] / DM;

    cudaFuncSetAttribute(gemm_kernel, cudaFuncAttributeMaxDynamicSharedMemorySize,
                         GEMM_SMEM_BYTES);

    init_kernel<<<1, 32>>>();
    w1cvt_kernel<<<dim3(DM / 32, DH / 32), 256>>>(w1);
    gemm_kernel<<<(n + BM - 1) / BM, 256, GEMM_SMEM_BYTES>>>(x, b1, qm, vm, n);
    window_kernel<<<dim3((n + CHW - 1) / CHW, NH), 256>>>(n, wp);
    final_kernel<<<1, 32>>>((float*)d_out);
}